// round 2
// baseline (speedup 1.0000x reference)
#include <cuda_runtime.h>
#include <cuda_bf16.h>
#include <cstdint>

// ---------------------------------------------------------------------------
// Problem constants (from reference)
// ---------------------------------------------------------------------------
#define N_TABLES 64
#define VOCAB    1024
#define D_EA     128
#define D_CONT   129          // D_EA + 1
#define MAXDAY   3650
#define P129     132          // padded stride for pe129 so rows are 16B aligned

// ---------------------------------------------------------------------------
// Scratch (device globals; no allocation allowed)
// ---------------------------------------------------------------------------
__device__ __align__(16) double g_invdiv129[P129];
__device__ __align__(16) double g_invdiv128[D_EA];
__device__ __align__(16) float  g_pe129[MAXDAY * P129];   // ~1.93 MB
__device__ __align__(16) float  g_pe128[MAXDAY * D_EA];   // ~1.87 MB

// ---------------------------------------------------------------------------
// Stage 1: inverse div_term per dim (double pow, 257 values total)
// ---------------------------------------------------------------------------
__global__ void k_invdiv() {
    int k = threadIdx.x;
    if (k < D_CONT) {
        int e = (k & 1) ? (k - 1) : k;
        g_invdiv129[k] = 1.0 / pow(10000.0, (double)e / (double)D_CONT);
    }
    if (k < D_EA) {
        int e = (k & 1) ? (k - 1) : k;
        g_invdiv128[k] = 1.0 / pow(10000.0, (double)e / (double)D_EA);
    }
}

// ---------------------------------------------------------------------------
// Stage 2: PE tables. ang reduced mod 2*pi in double, then single-precision
// sin/cos on |r| <= pi  (accurate even if sinf -> __sinf under fast-math).
// ---------------------------------------------------------------------------
__global__ void k_pe() {
    int tid = blockIdx.x * blockDim.x + threadIdx.x;
    const double TWO_PI     = 6.283185307179586476925286766559;
    const double INV_TWO_PI = 0.15915494309189533576888376337251;
    const int total129 = MAXDAY * D_CONT;
    if (tid < total129) {
        int day = tid / D_CONT;
        int k   = tid - day * D_CONT;
        double ang = (double)day * g_invdiv129[k];
        double r   = ang - rint(ang * INV_TWO_PI) * TWO_PI;
        float  f   = (float)r;
        g_pe129[day * P129 + k] = (k & 1) ? cosf(f) : sinf(f);
    } else {
        int t = tid - total129;
        if (t < MAXDAY * D_EA) {
            int day = t >> 7;          // /128
            int k   = t & 127;
            double ang = (double)day * g_invdiv128[k];
            double r   = ang - rint(ang * INV_TWO_PI) * TWO_PI;
            float  f   = (float)r;
            g_pe128[day * D_EA + k] = (k & 1) ? cosf(f) : sinf(f);
        }
    }
}

// ---------------------------------------------------------------------------
// Continuous branch: one warp per node, 129 outputs.
// Rows are 129 floats (not 16B aligned) -> strided scalar ld/st (coalesced).
// ---------------------------------------------------------------------------
__global__ void k_cont(const int* __restrict__ ids,
                       const float* __restrict__ vals,
                       const int* __restrict__ days,
                       const float* __restrict__ ea,
                       float* __restrict__ out, int n) {
    int w    = (blockIdx.x * blockDim.x + threadIdx.x) >> 5;
    int lane = threadIdx.x & 31;
    if (w >= n) return;
    int id  = __ldg(ids  + w);
    int day = __ldg(days + w);
    const float* earow = ea + id * D_EA;
    const float* perow = g_pe129 + day * P129;
    float* o = out + (long long)w * D_CONT;
#pragma unroll
    for (int j = 0; j < 4; j++) {
        int k = lane + 32 * j;
        o[k] = __ldg(earow + k) + perow[k];
    }
    if (lane == 0) o[D_EA] = __ldg(vals + w) + perow[D_EA];
}

// ---------------------------------------------------------------------------
// Categorical branch: one warp per node, 128 outputs, fully float4.
// ea rows, categ rows, pe128 rows, and out rows are all 512B aligned.
// ---------------------------------------------------------------------------
__global__ void k_categ(const int* __restrict__ ids,
                        const int* __restrict__ vocab,
                        const int* __restrict__ days,
                        const float4* __restrict__ ea4,
                        const float4* __restrict__ tab4,
                        float4* __restrict__ out4, int n) {
    int w    = (blockIdx.x * blockDim.x + threadIdx.x) >> 5;
    int lane = threadIdx.x & 31;
    if (w >= n) return;
    int id  = __ldg(ids   + w);
    int v   = __ldg(vocab + w);
    int day = __ldg(days  + w);

    float4 a = __ldg(ea4 + id * 32 + lane);
    float4 b = __ldg(tab4 + ((long long)id * VOCAB + v) * 32 + lane);
    const float4* pe4 = reinterpret_cast<const float4*>(g_pe128) + day * 32;
    float4 p = pe4[lane];

    float4 r;
    r.x = a.x + b.x + p.x;
    r.y = a.y + b.y + p.y;
    r.z = a.z + b.z + p.z;
    r.w = a.w + b.w + p.w;
    out4[(long long)w * 32 + lane] = r;
}

// Scalar fallback for categ if the output offset is not 16B aligned
// (only possible when n % 4 != 0).
__global__ void k_categ_scalar(const int* __restrict__ ids,
                               const int* __restrict__ vocab,
                               const int* __restrict__ days,
                               const float* __restrict__ ea,
                               const float* __restrict__ tab,
                               float* __restrict__ out, int n) {
    int w    = (blockIdx.x * blockDim.x + threadIdx.x) >> 5;
    int lane = threadIdx.x & 31;
    if (w >= n) return;
    int id  = __ldg(ids   + w);
    int v   = __ldg(vocab + w);
    int day = __ldg(days  + w);
    const float* earow = ea + id * D_EA;
    const float* trow  = tab + ((long long)id * VOCAB + v) * D_EA;
    const float* perow = g_pe128 + day * D_EA;
    float* o = out + (long long)w * D_EA;
#pragma unroll
    for (int j = 0; j < 4; j++) {
        int k = lane + 32 * j;
        o[k] = __ldg(earow + k) + __ldg(trow + k) + perow[k];
    }
}

// ---------------------------------------------------------------------------
// Launch
// ---------------------------------------------------------------------------
extern "C" void kernel_launch(void* const* d_in, const int* in_sizes, int n_in,
                              void* d_out, int out_size) {
    const int*   cont_ids   = (const int*)  d_in[0];
    const float* cont_vals  = (const float*)d_in[1];
    const int*   cont_days  = (const int*)  d_in[2];
    const int*   categ_ids  = (const int*)  d_in[3];
    const int*   categ_voc  = (const int*)  d_in[4];
    const int*   categ_days = (const int*)  d_in[5];
    const float* ea_table   = (const float*)d_in[6];
    const float* categ_tab  = (const float*)d_in[7];

    const int n = in_sizes[0];

    float* out       = (float*)d_out;
    float* out_categ = out + (long long)n * D_CONT;

    // Stage 1+2: build PE tables (every call; deterministic, ~5us)
    k_invdiv<<<1, 256>>>();
    {
        int total = MAXDAY * D_CONT + MAXDAY * D_EA;
        k_pe<<<(total + 255) / 256, 256>>>();
    }

    // Main kernels: one warp per node, 8 warps per 256-thread block.
    int blocks = (n + 7) / 8;
    k_cont<<<blocks, 256>>>(cont_ids, cont_vals, cont_days, ea_table, out, n);

    bool aligned = ((((long long)n * D_CONT) & 3) == 0) &&
                   ((((unsigned long long)(size_t)out_categ) & 15ULL) == 0ULL);
    if (aligned) {
        k_categ<<<blocks, 256>>>(categ_ids, categ_voc, categ_days,
                                 (const float4*)ea_table,
                                 (const float4*)categ_tab,
                                 (float4*)out_categ, n);
    } else {
        k_categ_scalar<<<blocks, 256>>>(categ_ids, categ_voc, categ_days,
                                        ea_table, categ_tab, out_categ, n);
    }
}